// round 7
// baseline (speedup 1.0000x reference)
#include <cuda_runtime.h>
#include <cstdint>

#define T_DIM 8192
#define D_DIM 5120
#define H_DIM 13824

#define BM 128
#define BN 224        // 96 tensor cols + 128 dp4a cols
#define BK 64
#define PITCH 80
#define A_BYTES (128 * PITCH)            // 10240
#define B_BYTES (224 * PITCH)            // 17920
#define STAGE_BYTES (A_BYTES + B_BYTES)  // 28160
#define SMEM_BYTES (2 * STAGE_BYTES)     // 56320

// ---------------- scratch (device globals: allocation-free rule) --------------
__device__ uint8_t d_w1u8[(size_t)H_DIM * D_DIM];
__device__ uint8_t d_w2u8[(size_t)D_DIM * H_DIM];
__device__ int8_t  d_q1[(size_t)T_DIM * D_DIM];
__device__ int8_t  d_q2[(size_t)T_DIM * H_DIM];
__device__ float   d_g [(size_t)T_DIM * H_DIM];
__device__ float   d_s1[T_DIM];
__device__ int     d_sum1[T_DIM];
__device__ float   d_s2[T_DIM];
__device__ int     d_sum2[T_DIM];

// ---------------- weight pack: int32 code [0,255] -> u8 raw -------------------
__global__ void convert_weights(const int* __restrict__ w, uint8_t* __restrict__ o, int n4) {
    int i = blockIdx.x * blockDim.x + threadIdx.x;
    if (i < n4) {
        int4 v = ((const int4*)w)[i];
        unsigned p = (unsigned)(v.x & 0xff)
                   | ((unsigned)(v.y & 0xff) << 8)
                   | ((unsigned)(v.z & 0xff) << 16)
                   | ((unsigned)(v.w & 0xff) << 24);
        ((unsigned*)o)[i] = p;
    }
}

// ---------------- per-row dynamic int8 quant ----------------------------------
template<int THREADS, int V>
__global__ void quant_rows(const float* __restrict__ x, int8_t* __restrict__ q,
                           float* __restrict__ s_out, int* __restrict__ sum_out,
                           int cols) {
    constexpr int NW = THREADS / 32;
    __shared__ float smax[NW];
    __shared__ int   ssum[NW];
    int row  = blockIdx.x;
    int tid  = threadIdx.x;
    int lane = tid & 31, w = tid >> 5;

    const float4* xr = (const float4*)(x + (size_t)row * cols);
    float4 v[V];
    float m = 0.0f;
#pragma unroll
    for (int i = 0; i < V; i++) {
        v[i] = xr[i * THREADS + tid];
        m = fmaxf(m, fmaxf(fmaxf(fabsf(v[i].x), fabsf(v[i].y)),
                           fmaxf(fabsf(v[i].z), fabsf(v[i].w))));
    }
#pragma unroll
    for (int o = 16; o; o >>= 1) m = fmaxf(m, __shfl_xor_sync(0xffffffffu, m, o));
    if (lane == 0) smax[w] = m;
    __syncthreads();
    if (tid == 0) {
        float mm = smax[0];
#pragma unroll
        for (int i = 1; i < NW; i++) mm = fmaxf(mm, smax[i]);
        smax[0] = mm;
    }
    __syncthreads();
    m = smax[0];

    float s = fmaxf(__fdiv_rn(m, 127.0f), 1e-8f);

    unsigned* qo = (unsigned*)(q + (size_t)row * cols);
    int isum = 0;
#pragma unroll
    for (int i = 0; i < V; i++) {
        float fs[4] = {v[i].x, v[i].y, v[i].z, v[i].w};
        int qi[4];
#pragma unroll
        for (int c = 0; c < 4; c++) {
            float r = rintf(__fdiv_rn(fs[c], s));
            r = fminf(fmaxf(r, -127.0f), 127.0f);
            qi[c] = (int)r;
            isum += qi[c];
        }
        unsigned p = (unsigned)(qi[0] & 0xff)
                   | ((unsigned)(qi[1] & 0xff) << 8)
                   | ((unsigned)(qi[2] & 0xff) << 16)
                   | ((unsigned)(qi[3] & 0xff) << 24);
        qo[i * THREADS + tid] = p;
    }
#pragma unroll
    for (int o = 16; o; o >>= 1) isum += __shfl_xor_sync(0xffffffffu, isum, o);
    if (lane == 0) ssum[w] = isum;
    __syncthreads();
    if (tid == 0) {
        int t = 0;
#pragma unroll
        for (int i = 0; i < NW; i++) t += ssum[i];
        sum_out[row] = t;
        s_out[row]   = s;
    }
}

// ================= hybrid GEMM: tensor (96 cols) + dp4a (128 cols) ============
__device__ __forceinline__ uint32_t swoff(int row, int chunk) {
    return (uint32_t)(row * PITCH + ((chunk ^ ((row >> 3) & 3)) << 4));
}

__device__ __forceinline__ void mma_s8u8(int* c, const int* a, const int* b) {
    asm volatile(
        "mma.sync.aligned.m16n8k32.row.col.s32.s8.u8.s32 "
        "{%0,%1,%2,%3}, {%4,%5,%6,%7}, {%8,%9}, {%0,%1,%2,%3};\n"
        : "+r"(c[0]), "+r"(c[1]), "+r"(c[2]), "+r"(c[3])
        : "r"(a[0]), "r"(a[1]), "r"(a[2]), "r"(a[3]), "r"(b[0]), "r"(b[1]));
}

__device__ __forceinline__ int dp4a_su(int a, int b, int c) {
    int d;
    asm("dp4a.s32.u32 %0, %1, %2, %3;" : "=r"(d) : "r"(a), "r"(b), "r"(c));
    return d;
}

__device__ __forceinline__ float gelu_exact(float v) {
    return v * (erff(__fdiv_rn(v, 1.41421356237309515f)) + 1.0f) * 0.5f;
}

__device__ __forceinline__ void cp16(uint32_t dst, const void* src) {
    asm volatile("cp.async.cg.shared.global [%0], [%1], 16;\n" :: "r"(dst), "l"(src));
}
#define CP_COMMIT() asm volatile("cp.async.commit_group;\n" ::: "memory")
#define CP_WAIT0()  asm volatile("cp.async.wait_group 0;\n" ::: "memory")

template<bool DO_GELU>
__global__ __launch_bounds__(512, 1)
void gemm_hybrid(const int8_t* __restrict__ A, const uint8_t* __restrict__ B,
                 float* __restrict__ C, int K, int N,
                 const float* __restrict__ sA, const int* __restrict__ sumA,
                 const float* __restrict__ sW, const float* __restrict__ zp,
                 const float* __restrict__ bias) {
    extern __shared__ int8_t smem[];
    uint32_t smu;
    asm("{ .reg .u64 t; cvta.to.shared.u64 t, %1; cvt.u32.u64 %0, t; }"
        : "=r"(smu) : "l"(smem));

    int tid = threadIdx.x;
    int bm = blockIdx.y * BM, bn = blockIdx.x * BN;
    int KT = K >> 6;

    int lane = tid & 31, wid = tid >> 5;
    // tensor role (wid 0-7): 2 warpM x 4 warpN, cols 0..95
    int warpM = wid >> 2, warpN = wid & 3;
    int arowL = warpM * 64 + (lane >> 2);
    int browL = warpN * 24 + (lane >> 2);
    int koff  = (lane & 3) * 4;
    // dp4a role (wid 8-15): 256 threads, 16x16, each 8 rows x 8 cols (96..223)
    int dtid = tid - 256;
    int tRow = dtid >> 4, tCol = dtid & 15;

    // -------- staging: A chunk tid, B chunk tid, B chunk 512+tid (tid<384)
    int r0 = tid >> 2, c0 = tid & 3;
    const int8_t* gA  = A + (size_t)(bm + r0) * K + c0 * 16;
    int br1 = min(bn + r0, N - 1);
    const int8_t* gB1 = (const int8_t*)B + (size_t)br1 * K + c0 * 16;
    int r2 = 128 + r0;
    int br2 = min(bn + r2, N - 1);
    const int8_t* gB2 = (const int8_t*)B + (size_t)br2 * K + c0 * 16;
    uint32_t soA  = swoff(r0, c0);
    uint32_t soB1 = (uint32_t)A_BYTES + swoff(r0, c0);
    uint32_t soB2 = (uint32_t)A_BYTES + swoff(r2, c0);

    auto stage = [&](uint32_t sbase, int kt) {
        int k0 = kt * BK;
        cp16(sbase + soA,  gA  + k0);
        cp16(sbase + soB1, gB1 + k0);
        if (tid < 384) cp16(sbase + soB2, gB2 + k0);
    };

    int acc[64];
#pragma unroll
    for (int i = 0; i < 64; i++) acc[i] = 0;

    // prologue
    stage(smu, 0);
    CP_COMMIT();
    CP_WAIT0();
    __syncthreads();

    for (int kt = 0; kt < KT; kt++) {
        int cur = kt & 1;
        bool pf = (kt + 1) < KT;
        if (pf) {
            stage(smu + (cur ^ 1) * STAGE_BYTES, kt + 1);
            CP_COMMIT();
        }
        const int8_t* Asb = smem + cur * STAGE_BYTES;
        const int8_t* Bsb = Asb + A_BYTES;

        if (tid < 256) {                          // ---- tensor warps ----
#pragma unroll
            for (int ks = 0; ks < 2; ks++) {
                int a[4][4], b[3][2];
                int cc0 = ks * 2, cc1 = cc0 + 1;
#pragma unroll
                for (int mi = 0; mi < 4; mi++) {
                    int ra = arowL + mi * 16, rb = ra + 8;
                    a[mi][0] = *(const int*)(Asb + swoff(ra, cc0) + koff);
                    a[mi][1] = *(const int*)(Asb + swoff(rb, cc0) + koff);
                    a[mi][2] = *(const int*)(Asb + swoff(ra, cc1) + koff);
                    a[mi][3] = *(const int*)(Asb + swoff(rb, cc1) + koff);
                }
#pragma unroll
                for (int ni = 0; ni < 3; ni++) {
                    int rb = browL + ni * 8;
                    b[ni][0] = *(const int*)(Bsb + swoff(rb, cc0) + koff);
                    b[ni][1] = *(const int*)(Bsb + swoff(rb, cc1) + koff);
                }
#pragma unroll
                for (int mi = 0; mi < 4; mi++)
#pragma unroll
                    for (int ni = 0; ni < 3; ni++)
                        mma_s8u8(&acc[(mi * 3 + ni) * 4], a[mi], b[ni]);
            }
        } else {                                  // ---- dp4a warps ----
#pragma unroll
            for (int cc4 = 0; cc4 < 4; cc4++) {
                int c = (cc4 + tCol) & 3;         // chunk rotation (bank spread)
                int4 a4[8];
#pragma unroll
                for (int i = 0; i < 8; i++)
                    a4[i] = *(const int4*)(Asb + swoff(tRow * 8 + i, c));
#pragma unroll
                for (int j = 0; j < 8; j++) {
                    int4 b4 = *(const int4*)(Bsb + swoff(96 + tCol * 8 + j, c));
                    const int* bw = (const int*)&b4;
#pragma unroll
                    for (int w = 0; w < 4; w++)
#pragma unroll
                        for (int i = 0; i < 8; i++)
                            acc[i * 8 + j] = dp4a_su(((const int*)&a4[i])[w], bw[w], acc[i * 8 + j]);
                }
            }
        }

        if (pf) CP_WAIT0();
        __syncthreads();
    }

    // ---- epilogues: dequant (+GELU) ----
    if (tid < 256) {                              // tensor cols 0..95 (always interior)
#pragma unroll
        for (int mi = 0; mi < 4; mi++) {
#pragma unroll
            for (int half = 0; half < 2; half++) {
                int r = bm + warpM * 64 + mi * 16 + (lane >> 2) + half * 8;
                float sa   = __ldg(&sA[r]);
                float fsum = (float)__ldg(&sumA[r]);
                float* Crow = C + (size_t)r * N;
#pragma unroll
                for (int ni = 0; ni < 3; ni++) {
                    int cc = bn + warpN * 24 + ni * 8 + (lane & 3) * 2;
                    float f0 = (float)acc[(mi * 3 + ni) * 4 + half * 2 + 0];
                    float f1 = (float)acc[(mi * 3 + ni) * 4 + half * 2 + 1];
                    float v0 = (sa * __ldg(&sW[cc]))     * (f0 - __ldg(&zp[cc])     * fsum) + __ldg(&bias[cc]);
                    float v1 = (sa * __ldg(&sW[cc + 1])) * (f1 - __ldg(&zp[cc + 1]) * fsum) + __ldg(&bias[cc + 1]);
                    if (DO_GELU) { v0 = gelu_exact(v0); v1 = gelu_exact(v1); }
                    *(float2*)(Crow + cc) = make_float2(v0, v1);
                }
            }
        }
    } else {                                      // dp4a cols 96..223 (N-guarded)
        int cbase = bn + 96 + tCol * 8;
#pragma unroll
        for (int i = 0; i < 8; i++) {
            int r = bm + tRow * 8 + i;
            float sa   = __ldg(&sA[r]);
            float fsum = (float)__ldg(&sumA[r]);
            float* Crow = C + (size_t)r * N;
#pragma unroll
            for (int j = 0; j < 8; j++) {
                int cc = cbase + j;
                if (cc < N) {
                    float f = (float)acc[i * 8 + j];
                    float v = (sa * __ldg(&sW[cc])) * (f - __ldg(&zp[cc]) * fsum) + __ldg(&bias[cc]);
                    if (DO_GELU) v = gelu_exact(v);
                    Crow[cc] = v;
                }
            }
        }
    }
}

// ---------------- launch -------------------------------------------------------
extern "C" void kernel_launch(void* const* d_in, const int* in_sizes, int n_in,
                              void* d_out, int out_size) {
    const float* x    = (const float*)d_in[0];
    const int*   w1q  = (const int*)  d_in[1];
    const float* w1s  = (const float*)d_in[2];
    const float* w1zp = (const float*)d_in[3];
    const float* b1   = (const float*)d_in[4];
    const int*   w2q  = (const int*)  d_in[5];
    const float* w2s  = (const float*)d_in[6];
    const float* w2zp = (const float*)d_in[7];
    const float* b2   = (const float*)d_in[8];
    float* out = (float*)d_out;

    uint8_t *w1u8, *w2u8;
    int8_t *q1, *q2;
    float *g, *s1, *s2;
    int *sum1, *sum2;
    cudaGetSymbolAddress((void**)&w1u8, d_w1u8);
    cudaGetSymbolAddress((void**)&w2u8, d_w2u8);
    cudaGetSymbolAddress((void**)&q1,   d_q1);
    cudaGetSymbolAddress((void**)&q2,   d_q2);
    cudaGetSymbolAddress((void**)&g,    d_g);
    cudaGetSymbolAddress((void**)&s1,   d_s1);
    cudaGetSymbolAddress((void**)&s2,   d_s2);
    cudaGetSymbolAddress((void**)&sum1, d_sum1);
    cudaGetSymbolAddress((void**)&sum2, d_sum2);

    cudaFuncSetAttribute(gemm_hybrid<true>,
                         cudaFuncAttributeMaxDynamicSharedMemorySize, SMEM_BYTES);
    cudaFuncSetAttribute(gemm_hybrid<false>,
                         cudaFuncAttributeMaxDynamicSharedMemorySize, SMEM_BYTES);

    const int n4 = (int)(((size_t)H_DIM * D_DIM) / 4);
    convert_weights<<<(n4 + 255) / 256, 256>>>(w1q, w1u8, n4);
    convert_weights<<<(n4 + 255) / 256, 256>>>(w2q, w2u8, n4);

    quant_rows<320, 4><<<T_DIM, 320>>>(x, q1, s1, sum1, D_DIM);

    dim3 g1((H_DIM + BN - 1) / BN, T_DIM / BM);  // 62 x 64
    gemm_hybrid<true><<<g1, 512, SMEM_BYTES>>>(q1, w1u8, g, D_DIM, H_DIM,
                                               s1, sum1, w1s, w1zp, b1);

    quant_rows<384, 9><<<T_DIM, 384>>>(g, q2, s2, sum2, H_DIM);

    dim3 g2((D_DIM + BN - 1) / BN, T_DIM / BM);  // 23 x 64
    gemm_hybrid<false><<<g2, 512, SMEM_BYTES>>>(q2, w2u8, out, H_DIM, D_DIM,
                                                s2, sum2, w2s, w2zp, b2);
}

// round 8
// speedup vs baseline: 1.5299x; 1.5299x over previous
#include <cuda_runtime.h>
#include <cstdint>

#define T_DIM 8192
#define D_DIM 5120
#define H_DIM 13824

#define BM 128
#define BN 224        // 128 tensor cols + 96 dp4a cols
#define BK 64
#define PITCH 80
#define A_BYTES (128 * PITCH)            // 10240
#define B_BYTES (224 * PITCH)            // 17920
#define STAGE_BYTES (A_BYTES + B_BYTES)  // 28160
#define STAGES 3
#define SMEM_BYTES (STAGES * STAGE_BYTES) // 84480

// ---------------- scratch (device globals: allocation-free rule) --------------
__device__ uint8_t d_w1u8[(size_t)H_DIM * D_DIM];
__device__ uint8_t d_w2u8[(size_t)D_DIM * H_DIM];
__device__ int8_t  d_q1[(size_t)T_DIM * D_DIM];
__device__ int8_t  d_q2[(size_t)T_DIM * H_DIM];
__device__ float   d_g [(size_t)T_DIM * H_DIM];
__device__ float   d_s1[T_DIM];
__device__ int     d_sum1[T_DIM];
__device__ float   d_s2[T_DIM];
__device__ int     d_sum2[T_DIM];

// ---------------- weight pack: int32 code [0,255] -> u8 raw -------------------
__global__ void convert_weights(const int* __restrict__ w, uint8_t* __restrict__ o, int n4) {
    int i = blockIdx.x * blockDim.x + threadIdx.x;
    if (i < n4) {
        int4 v = ((const int4*)w)[i];
        unsigned p = (unsigned)(v.x & 0xff)
                   | ((unsigned)(v.y & 0xff) << 8)
                   | ((unsigned)(v.z & 0xff) << 16)
                   | ((unsigned)(v.w & 0xff) << 24);
        ((unsigned*)o)[i] = p;
    }
}

// ---------------- per-row dynamic int8 quant ----------------------------------
template<int THREADS, int V>
__global__ void quant_rows(const float* __restrict__ x, int8_t* __restrict__ q,
                           float* __restrict__ s_out, int* __restrict__ sum_out,
                           int cols) {
    constexpr int NW = THREADS / 32;
    __shared__ float smax[NW];
    __shared__ int   ssum[NW];
    int row  = blockIdx.x;
    int tid  = threadIdx.x;
    int lane = tid & 31, w = tid >> 5;

    const float4* xr = (const float4*)(x + (size_t)row * cols);
    float4 v[V];
    float m = 0.0f;
#pragma unroll
    for (int i = 0; i < V; i++) {
        v[i] = xr[i * THREADS + tid];
        m = fmaxf(m, fmaxf(fmaxf(fabsf(v[i].x), fabsf(v[i].y)),
                           fmaxf(fabsf(v[i].z), fabsf(v[i].w))));
    }
#pragma unroll
    for (int o = 16; o; o >>= 1) m = fmaxf(m, __shfl_xor_sync(0xffffffffu, m, o));
    if (lane == 0) smax[w] = m;
    __syncthreads();
    if (tid == 0) {
        float mm = smax[0];
#pragma unroll
        for (int i = 1; i < NW; i++) mm = fmaxf(mm, smax[i]);
        smax[0] = mm;
    }
    __syncthreads();
    m = smax[0];

    float s = fmaxf(__fdiv_rn(m, 127.0f), 1e-8f);

    unsigned* qo = (unsigned*)(q + (size_t)row * cols);
    int isum = 0;
#pragma unroll
    for (int i = 0; i < V; i++) {
        float fs[4] = {v[i].x, v[i].y, v[i].z, v[i].w};
        int qi[4];
#pragma unroll
        for (int c = 0; c < 4; c++) {
            float r = rintf(__fdiv_rn(fs[c], s));
            r = fminf(fmaxf(r, -127.0f), 127.0f);
            qi[c] = (int)r;
            isum += qi[c];
        }
        unsigned p = (unsigned)(qi[0] & 0xff)
                   | ((unsigned)(qi[1] & 0xff) << 8)
                   | ((unsigned)(qi[2] & 0xff) << 16)
                   | ((unsigned)(qi[3] & 0xff) << 24);
        qo[i * THREADS + tid] = p;
    }
#pragma unroll
    for (int o = 16; o; o >>= 1) isum += __shfl_xor_sync(0xffffffffu, isum, o);
    if (lane == 0) ssum[w] = isum;
    __syncthreads();
    if (tid == 0) {
        int t = 0;
#pragma unroll
        for (int i = 0; i < NW; i++) t += ssum[i];
        sum_out[row] = t;
        s_out[row]   = s;
    }
}

// ================= hybrid GEMM: tensor (128 cols) + dp4a (96 cols) ============
__device__ __forceinline__ uint32_t swoff(int row, int chunk) {
    return (uint32_t)(row * PITCH + ((chunk ^ ((row >> 3) & 3)) << 4));
}

__device__ __forceinline__ void mma_s8u8(int* c, const int* a, const int* b) {
    asm volatile(
        "mma.sync.aligned.m16n8k32.row.col.s32.s8.u8.s32 "
        "{%0,%1,%2,%3}, {%4,%5,%6,%7}, {%8,%9}, {%0,%1,%2,%3};\n"
        : "+r"(c[0]), "+r"(c[1]), "+r"(c[2]), "+r"(c[3])
        : "r"(a[0]), "r"(a[1]), "r"(a[2]), "r"(a[3]), "r"(b[0]), "r"(b[1]));
}

__device__ __forceinline__ int dp4a_su(int a, int b, int c) {
    int d;
    asm("dp4a.s32.u32 %0, %1, %2, %3;" : "=r"(d) : "r"(a), "r"(b), "r"(c));
    return d;
}

__device__ __forceinline__ float gelu_exact(float v) {
    return v * (erff(__fdiv_rn(v, 1.41421356237309515f)) + 1.0f) * 0.5f;
}

__device__ __forceinline__ void cp16(uint32_t dst, const void* src) {
    asm volatile("cp.async.cg.shared.global [%0], [%1], 16;\n" :: "r"(dst), "l"(src));
}
#define CP_COMMIT() asm volatile("cp.async.commit_group;\n" ::: "memory")
#define CP_WAIT0()  asm volatile("cp.async.wait_group 0;\n" ::: "memory")
#define CP_WAIT1()  asm volatile("cp.async.wait_group 1;\n" ::: "memory")

template<bool DO_GELU>
__global__ __launch_bounds__(512, 1)
void gemm_hybrid(const int8_t* __restrict__ A, const uint8_t* __restrict__ B,
                 float* __restrict__ C, int K, int N,
                 const float* __restrict__ sA, const int* __restrict__ sumA,
                 const float* __restrict__ sW, const float* __restrict__ zp,
                 const float* __restrict__ bias) {
    extern __shared__ int8_t smem[];
    uint32_t smu;
    asm("{ .reg .u64 t; cvta.to.shared.u64 t, %1; cvt.u32.u64 %0, t; }"
        : "=r"(smu) : "l"(smem));

    int tid = threadIdx.x;
    int bm = blockIdx.y * BM, bn = blockIdx.x * BN;
    int KT = K >> 6;

    int lane = tid & 31, wid = tid >> 5;
    // tensor role (wid 0-7): 2 warpM x 4 warpN, cols 0..127 (4 n-frags)
    int warpM = wid >> 2, warpN = wid & 3;
    int arowL = warpM * 64 + (lane >> 2);
    int browL = warpN * 32 + (lane >> 2);
    int koff  = (lane & 3) * 4;
    // dp4a role (wid 8-15): 256 threads, 16x16; rows 8*tRow..+8, cols 128+6*tCol..+6
    int dtid = tid - 256;
    int tRow = dtid >> 4, tCol = dtid & 15;

    // -------- staging: A chunk tid, B chunk tid, B chunk 512+tid (tid<384)
    int r0 = tid >> 2, c0 = tid & 3;
    const int8_t* gA  = A + (size_t)(bm + r0) * K + c0 * 16;
    int br1 = min(bn + r0, N - 1);
    const int8_t* gB1 = (const int8_t*)B + (size_t)br1 * K + c0 * 16;
    int r2 = 128 + r0;
    int br2 = min(bn + r2, N - 1);
    const int8_t* gB2 = (const int8_t*)B + (size_t)br2 * K + c0 * 16;
    uint32_t soA  = swoff(r0, c0);
    uint32_t soB1 = (uint32_t)A_BYTES + swoff(r0, c0);
    uint32_t soB2 = (uint32_t)A_BYTES + swoff(r2, c0);

    auto stage = [&](uint32_t sbase, int kt) {
        int k0 = kt * BK;
        cp16(sbase + soA,  gA  + k0);
        cp16(sbase + soB1, gB1 + k0);
        if (tid < 384) cp16(sbase + soB2, gB2 + k0);
    };

    int acc[64];
#pragma unroll
    for (int i = 0; i < 64; i++) acc[i] = 0;

    // prologue: stages 0 and 1 in flight; wait for stage 0 only
    stage(smu, 0);
    CP_COMMIT();
    stage(smu + STAGE_BYTES, 1);
    CP_COMMIT();
    CP_WAIT1();
    __syncthreads();

    for (int kt = 0; kt < KT; kt++) {
        int cur = kt % STAGES;
        bool pf = (kt + 2) < KT;
        if (pf) {
            stage(smu + ((kt + 2) % STAGES) * STAGE_BYTES, kt + 2);
            CP_COMMIT();
        }
        const int8_t* Asb = smem + cur * STAGE_BYTES;
        const int8_t* Bsb = Asb + A_BYTES;

        if (tid < 256) {                          // ---- tensor warps (128 cols) ----
#pragma unroll
            for (int ks = 0; ks < 2; ks++) {
                int a[4][4], b[4][2];
                int cc0 = ks * 2, cc1 = cc0 + 1;
#pragma unroll
                for (int mi = 0; mi < 4; mi++) {
                    int ra = arowL + mi * 16, rb = ra + 8;
                    a[mi][0] = *(const int*)(Asb + swoff(ra, cc0) + koff);
                    a[mi][1] = *(const int*)(Asb + swoff(rb, cc0) + koff);
                    a[mi][2] = *(const int*)(Asb + swoff(ra, cc1) + koff);
                    a[mi][3] = *(const int*)(Asb + swoff(rb, cc1) + koff);
                }
#pragma unroll
                for (int ni = 0; ni < 4; ni++) {
                    int rb = browL + ni * 8;
                    b[ni][0] = *(const int*)(Bsb + swoff(rb, cc0) + koff);
                    b[ni][1] = *(const int*)(Bsb + swoff(rb, cc1) + koff);
                }
#pragma unroll
                for (int mi = 0; mi < 4; mi++)
#pragma unroll
                    for (int ni = 0; ni < 4; ni++)
                        mma_s8u8(&acc[(mi * 4 + ni) * 4], a[mi], b[ni]);
            }
        } else {                                  // ---- dp4a warps (96 cols) ----
#pragma unroll
            for (int cc4 = 0; cc4 < 4; cc4++) {
                int c = (cc4 + tCol) & 3;         // chunk rotation (bank spread)
                int4 a4[8];
#pragma unroll
                for (int i = 0; i < 8; i++)
                    a4[i] = *(const int4*)(Asb + swoff(tRow * 8 + i, c));
#pragma unroll
                for (int j = 0; j < 6; j++) {
                    int4 b4 = *(const int4*)(Bsb + swoff(128 + tCol * 6 + j, c));
                    const int* bw = (const int*)&b4;
#pragma unroll
                    for (int w = 0; w < 4; w++)
#pragma unroll
                        for (int i = 0; i < 8; i++)
                            acc[i * 6 + j] = dp4a_su(((const int*)&a4[i])[w], bw[w], acc[i * 6 + j]);
                }
            }
        }

        if (kt + 1 < KT) {
            if (pf) CP_WAIT1();   // group kt+1 complete; kt+2 stays in flight
            else    CP_WAIT0();
        }
        __syncthreads();
    }

    // ---- epilogues: dequant (+GELU) ----
    if (tid < 256) {                              // tensor cols 0..127 (always interior)
#pragma unroll
        for (int mi = 0; mi < 4; mi++) {
#pragma unroll
            for (int half = 0; half < 2; half++) {
                int r = bm + warpM * 64 + mi * 16 + (lane >> 2) + half * 8;
                float sa   = __ldg(&sA[r]);
                float fsum = (float)__ldg(&sumA[r]);
                float* Crow = C + (size_t)r * N;
#pragma unroll
                for (int ni = 0; ni < 4; ni++) {
                    int cc = bn + warpN * 32 + ni * 8 + (lane & 3) * 2;
                    float f0 = (float)acc[(mi * 4 + ni) * 4 + half * 2 + 0];
                    float f1 = (float)acc[(mi * 4 + ni) * 4 + half * 2 + 1];
                    float v0 = (sa * __ldg(&sW[cc]))     * (f0 - __ldg(&zp[cc])     * fsum) + __ldg(&bias[cc]);
                    float v1 = (sa * __ldg(&sW[cc + 1])) * (f1 - __ldg(&zp[cc + 1]) * fsum) + __ldg(&bias[cc + 1]);
                    if (DO_GELU) { v0 = gelu_exact(v0); v1 = gelu_exact(v1); }
                    *(float2*)(Crow + cc) = make_float2(v0, v1);
                }
            }
        }
    } else {                                      // dp4a cols 128..223 (N-guarded)
        int cbase = bn + 128 + tCol * 6;
#pragma unroll
        for (int i = 0; i < 8; i++) {
            int r = bm + tRow * 8 + i;
            float sa   = __ldg(&sA[r]);
            float fsum = (float)__ldg(&sumA[r]);
            float* Crow = C + (size_t)r * N;
#pragma unroll
            for (int j = 0; j < 6; j++) {
                int cc = cbase + j;
                if (cc < N) {
                    float f = (float)acc[i * 6 + j];
                    float v = (sa * __ldg(&sW[cc])) * (f - __ldg(&zp[cc]) * fsum) + __ldg(&bias[cc]);
                    if (DO_GELU) v = gelu_exact(v);
                    Crow[cc] = v;
                }
            }
        }
    }
}

// ---------------- launch -------------------------------------------------------
extern "C" void kernel_launch(void* const* d_in, const int* in_sizes, int n_in,
                              void* d_out, int out_size) {
    const float* x    = (const float*)d_in[0];
    const int*   w1q  = (const int*)  d_in[1];
    const float* w1s  = (const float*)d_in[2];
    const float* w1zp = (const float*)d_in[3];
    const float* b1   = (const float*)d_in[4];
    const int*   w2q  = (const int*)  d_in[5];
    const float* w2s  = (const float*)d_in[6];
    const float* w2zp = (const float*)d_in[7];
    const float* b2   = (const float*)d_in[8];
    float* out = (float*)d_out;

    uint8_t *w1u8, *w2u8;
    int8_t *q1, *q2;
    float *g, *s1, *s2;
    int *sum1, *sum2;
    cudaGetSymbolAddress((void**)&w1u8, d_w1u8);
    cudaGetSymbolAddress((void**)&w2u8, d_w2u8);
    cudaGetSymbolAddress((void**)&q1,   d_q1);
    cudaGetSymbolAddress((void**)&q2,   d_q2);
    cudaGetSymbolAddress((void**)&g,    d_g);
    cudaGetSymbolAddress((void**)&s1,   d_s1);
    cudaGetSymbolAddress((void**)&s2,   d_s2);
    cudaGetSymbolAddress((void**)&sum1, d_sum1);
    cudaGetSymbolAddress((void**)&sum2, d_sum2);

    cudaFuncSetAttribute(gemm_hybrid<true>,
                         cudaFuncAttributeMaxDynamicSharedMemorySize, SMEM_BYTES);
    cudaFuncSetAttribute(gemm_hybrid<false>,
                         cudaFuncAttributeMaxDynamicSharedMemorySize, SMEM_BYTES);

    const int n4 = (int)(((size_t)H_DIM * D_DIM) / 4);
    convert_weights<<<(n4 + 255) / 256, 256>>>(w1q, w1u8, n4);
    convert_weights<<<(n4 + 255) / 256, 256>>>(w2q, w2u8, n4);

    quant_rows<320, 4><<<T_DIM, 320>>>(x, q1, s1, sum1, D_DIM);

    dim3 g1((H_DIM + BN - 1) / BN, T_DIM / BM);  // 62 x 64
    gemm_hybrid<true><<<g1, 512, SMEM_BYTES>>>(q1, w1u8, g, D_DIM, H_DIM,
                                               s1, sum1, w1s, w1zp, b1);

    quant_rows<384, 9><<<T_DIM, 384>>>(g, q2, s2, sum2, H_DIM);

    dim3 g2((D_DIM + BN - 1) / BN, T_DIM / BM);  // 23 x 64
    gemm_hybrid<false><<<g2, 512, SMEM_BYTES>>>(q2, w2u8, out, H_DIM, D_DIM,
                                                s2, sum2, w2s, w2zp, b2);
}